// round 15
// baseline (speedup 1.0000x reference)
#include <cuda_runtime.h>
#include <cuda_fp16.h>
#include <math.h>

// Fixed problem dims: x[16384,2048], u[2048,2048]
#define DMODEL 2048
#define DM2 (DMODEL * DMODEL)
#define NTOK 16384

#define BM 128
#define BN 128
#define BK 64
#define NSTAGE 2
#define NTHREADS 128
#define APAD 72    // A smem row stride (halves): 36 words % 32 == 4 -> conflict-free
#define BPAD 136   // B smem row stride (halves): 68 words % 32 == 4 -> conflict-free
#define SMEM_BYTES ((NSTAGE * BM * APAD + NSTAGE * BK * BPAD) * 2)   // 71680 -> 3 CTAs/SM

// Epilogue modes
#define MODE_CAYLEY 1   // H1 = fp16(acc + I), H2 = fp16(2*(Cadd + acc))
#define MODE_ROTR   2   // D = rot(acc) fp32, H1 = fp16(rot(acc) + R)
#define MODE_H      3   // H1 = fp16(acc + Cadd?)
#define MODE_TOKEN  4   // D = acc + rot(Cadd)

// ---------------------------------------------------------------------------
// Scratch (static device globals -- no allocation in kernel_launch)
// ---------------------------------------------------------------------------
__device__ float g_Ta[DM2], g_Tb[DM2];      // T per layer (fp32)
__device__ float g_D0[DM2];                 // D0 = rot(E1)
__device__ __half g_T16a[DM2], g_T16b[DM2];
__device__ __half g_Fa[DM2], g_Ga[DM2];
__device__ __half g_Fb[DM2], g_Gb[DM2];
__device__ __half g_BR[DM2];                // fp16(R + D0)
__device__ __half g_E2[DM2];                // fp16(E2)
__device__ __half g_DL[DM2];                // fp16(Delta)
__device__ __half g_X[NTOK * DMODEL];

// ---------------------------------------------------------------------------
// Elementwise kernels
// ---------------------------------------------------------------------------
__global__ void skew_batch_kernel(const float* __restrict__ W0, const float* __restrict__ W1,
                                  float* __restrict__ T0, float* __restrict__ T1,
                                  __half* __restrict__ H0, __half* __restrict__ H1) {
    int idx = blockIdx.x * blockDim.x + threadIdx.x;
    if (idx >= DM2) return;
    const float* W = blockIdx.y ? W1 : W0;
    float* T = blockIdx.y ? T1 : T0;
    __half* H = blockIdx.y ? H1 : H0;
    int i = idx / DMODEL;
    int j = idx % DMODEL;
    float v = 0.5f * (W[j * DMODEL + i] - W[idx]);
    T[idx] = v;
    H[idx] = __float2half_rn(v);
}

__global__ void cvt_kernel(const float* __restrict__ X, __half* __restrict__ H, int n) {
    int i = (blockIdx.x * blockDim.x + threadIdx.x) * 4;
    if (i >= n) return;
    float4 v = *(const float4*)(X + i);
    __half2* Hp = (__half2*)(H + i);
    Hp[0] = __floats2half2_rn(v.x, v.y);
    Hp[1] = __floats2half2_rn(v.z, v.w);
}

// ---------------------------------------------------------------------------
// Tensor-core GEMM, 128 threads / 4 warps, 64x64 warp tiles (minimal smem
// bytes-per-MAC), 128x128 CTA tile, 3 CTAs per SM. fp16 in, fp32 accumulate.
// row-major A[M,K], B[K,N]; M%128, N%128, K%64 == 0.
// 2-stage cp.async pipeline, BK=64. Fused epilogue modes + optional z-batch.
// ---------------------------------------------------------------------------
#define CPASYNC16(saddr, gptr) \
    asm volatile("cp.async.cg.shared.global [%0], [%1], 16;\n" :: "r"(saddr), "l"(gptr))
#define CP_COMMIT() asm volatile("cp.async.commit_group;\n" ::)
#define CP_WAIT(n)  asm volatile("cp.async.wait_group %0;\n" :: "n"(n))
#define LDSM4(r, addr) \
    asm volatile("ldmatrix.sync.aligned.m8n8.x4.shared.b16 {%0,%1,%2,%3}, [%4];\n" \
                 : "=r"((r)[0]), "=r"((r)[1]), "=r"((r)[2]), "=r"((r)[3]) : "r"(addr))
#define LDSM4T(r, addr) \
    asm volatile("ldmatrix.sync.aligned.m8n8.x4.trans.shared.b16 {%0,%1,%2,%3}, [%4];\n" \
                 : "=r"((r)[0]), "=r"((r)[1]), "=r"((r)[2]), "=r"((r)[3]) : "r"(addr))
#define MMA_F16(c, a, b) \
    asm volatile("mma.sync.aligned.m16n8k16.row.col.f32.f16.f16.f32 " \
                 "{%0,%1,%2,%3},{%4,%5,%6,%7},{%8,%9},{%0,%1,%2,%3};\n" \
                 : "+f"((c)[0]), "+f"((c)[1]), "+f"((c)[2]), "+f"((c)[3]) \
                 : "r"((a)[0]), "r"((a)[1]), "r"((a)[2]), "r"((a)[3]), \
                   "r"((b)[0]), "r"((b)[1]))

__device__ __forceinline__ int aoff(int s) { return s * (BM * APAD); }
__device__ __forceinline__ int boff(int s) { return NSTAGE * BM * APAD + s * (BK * BPAD); }

__global__ __launch_bounds__(NTHREADS, 3)
void hgemm_kernel(const __half* __restrict__ A0, const __half* __restrict__ B0,
                  const float* __restrict__ C0, float* __restrict__ D0_,
                  __half* __restrict__ H10, __half* __restrict__ H20, int mode0,
                  const __half* __restrict__ A1, const __half* __restrict__ B1,
                  const float* __restrict__ C1, float* __restrict__ D1_,
                  __half* __restrict__ H11, __half* __restrict__ H21, int mode1,
                  int M, int N, int K, const float* __restrict__ theta) {
    extern __shared__ __half sm[];
    const unsigned smbase = (unsigned)__cvta_generic_to_shared(sm);

    const int z = blockIdx.z;
    const __half* A = z ? A1 : A0;
    const __half* B = z ? B1 : B0;
    const float* Cadd = z ? C1 : C0;
    float* D = z ? D1_ : D0_;
    __half* H1 = z ? H11 : H10;
    __half* H2 = z ? H21 : H20;
    const int mode = z ? mode1 : mode0;

    const int tid = threadIdx.x;
    const int lane = tid & 31;
    const int warp = tid >> 5;       // 0..3
    const int wm = warp >> 1;        // 0..1  (64-row slab)
    const int wn = warp & 1;         // 0..1  (64-col slab)
    const int bm = blockIdx.y * BM;
    const int bn = blockIdx.x * BN;

    float c[4][8][4];
#pragma unroll
    for (int i = 0; i < 4; i++)
#pragma unroll
        for (int j = 0; j < 8; j++)
#pragma unroll
            for (int q = 0; q < 4; q++) c[i][j][q] = 0.0f;

    const int NIT = K / BK;

    auto load_stage = [&](int s, int k0) {
#pragma unroll
        for (int i = 0; i < 8; i++) {            // A: 128 rows x 64 cols = 1024 chunks
            int v = tid + (i << 7);              // 0..1023
            int ar = v >> 3, ac = (v & 7) * 8;
            const __half* ga = A + (size_t)(bm + ar) * K + k0 + ac;
            CPASYNC16(smbase + (unsigned)(aoff(s) + ar * APAD + ac) * 2, ga);
        }
#pragma unroll
        for (int i = 0; i < 8; i++) {            // B: 64 rows x 128 cols = 1024 chunks
            int v = tid + (i << 7);              // 0..1023
            int br = v >> 4, bc = (v & 15) * 8;
            const __half* gb = B + (size_t)(k0 + br) * N + bn + bc;
            CPASYNC16(smbase + (unsigned)(boff(s) + br * BPAD + bc) * 2, gb);
        }
        CP_COMMIT();
    };

    auto compute_stage = [&](int s) {
#pragma unroll
        for (int ks = 0; ks < 4; ks++) {         // 4 k-slices of 16
            unsigned ar[4][4];
#pragma unroll
            for (int i = 0; i < 4; i++) {
                int row = wm * 64 + i * 16 + (lane & 15);
                int col = ((lane >> 4) << 3) + ks * 16;
                LDSM4(ar[i], smbase + (unsigned)(aoff(s) + row * APAD + col) * 2);
            }
#pragma unroll
            for (int th = 0; th < 2; th++) {     // two 32-col halves of 64-col slab
                unsigned br[4][2];
#pragma unroll
                for (int t = 0; t < 2; t++) {
                    int row = ks * 16 + (lane & 15);
                    int col = wn * 64 + th * 32 + t * 16 + ((lane >> 4) << 3);
                    unsigned r[4];
                    LDSM4T(r, smbase + (unsigned)(boff(s) + row * BPAD + col) * 2);
                    br[t * 2][0] = r[0]; br[t * 2][1] = r[1];
                    br[t * 2 + 1][0] = r[2]; br[t * 2 + 1][1] = r[3];
                }
#pragma unroll
                for (int i = 0; i < 4; i++)
#pragma unroll
                    for (int j = 0; j < 4; j++)
                        MMA_F16(c[i][th * 4 + j], ar[i], br[j]);
            }
        }
    };

    load_stage(0, 0);

    for (int it = 0; it < NIT; ++it) {
        CP_WAIT(0);
        __syncthreads();    // stage it ready; all warps done computing stage it-1
        if (it + 1 < NIT) load_stage((it + 1) & 1, (it + 1) * BK);
        compute_stage(it & 1);
    }

    // ---- epilogue ----
    float rc = 1.0f, rs = 0.0f;
    if (mode == MODE_ROTR || mode == MODE_TOKEN) {
        float th = *theta;
        rc = cosf(th);
        rs = sinf(th);
    }
    const int gr = lane >> 2;
    const int gc = lane & 3;

#pragma unroll
    for (int i = 0; i < 4; i++) {
#pragma unroll
        for (int j = 0; j < 8; j++) {
            int row0 = bm + wm * 64 + i * 16 + gr;
            int row1 = row0 + 8;
            int col = bn + wn * 64 + j * 8 + gc * 2;    // even: aligned Givens pair
            size_t o0 = (size_t)row0 * N + col;
            size_t o1 = (size_t)row1 * N + col;
            float2 v0 = make_float2(c[i][j][0], c[i][j][1]);
            float2 v1 = make_float2(c[i][j][2], c[i][j][3]);

            if (mode == MODE_CAYLEY) {
                float2 t0 = *(const float2*)(Cadd + o0);
                float2 t1 = *(const float2*)(Cadd + o1);
                float f0x = v0.x + (row0 == col ? 1.0f : 0.0f);
                float f0y = v0.y + (row0 == col + 1 ? 1.0f : 0.0f);
                float f1x = v1.x + (row1 == col ? 1.0f : 0.0f);
                float f1y = v1.y + (row1 == col + 1 ? 1.0f : 0.0f);
                *(__half2*)(H1 + o0) = __floats2half2_rn(f0x, f0y);
                *(__half2*)(H1 + o1) = __floats2half2_rn(f1x, f1y);
                *(__half2*)(H2 + o0) = __floats2half2_rn(2.0f * (t0.x + v0.x),
                                                         2.0f * (t0.y + v0.y));
                *(__half2*)(H2 + o1) = __floats2half2_rn(2.0f * (t1.x + v1.x),
                                                         2.0f * (t1.y + v1.y));
            } else if (mode == MODE_ROTR) {
                float2 r0 = make_float2(v0.x * rc - v0.y * rs, v0.x * rs + v0.y * rc);
                float2 r1 = make_float2(v1.x * rc - v1.y * rs, v1.x * rs + v1.y * rc);
                *(float2*)(D + o0) = r0;
                *(float2*)(D + o1) = r1;
                float a0x = (row0 == col ? rc : (row0 == col + 1 ? -rs : 0.0f));
                float a0y = (row0 == col ? rs : (row0 == col + 1 ?  rc : 0.0f));
                float a1x = (row1 == col ? rc : (row1 == col + 1 ? -rs : 0.0f));
                float a1y = (row1 == col ? rs : (row1 == col + 1 ?  rc : 0.0f));
                *(__half2*)(H1 + o0) = __floats2half2_rn(r0.x + a0x, r0.y + a0y);
                *(__half2*)(H1 + o1) = __floats2half2_rn(r1.x + a1x, r1.y + a1y);
            } else if (mode == MODE_H) {
                if (Cadd) {
                    float2 a0 = *(const float2*)(Cadd + o0);
                    float2 a1 = *(const float2*)(Cadd + o1);
                    v0.x += a0.x; v0.y += a0.y;
                    v1.x += a1.x; v1.y += a1.y;
                }
                *(__half2*)(H1 + o0) = __floats2half2_rn(v0.x, v0.y);
                *(__half2*)(H1 + o1) = __floats2half2_rn(v1.x, v1.y);
            } else {  // MODE_TOKEN
                float2 a0 = *(const float2*)(Cadd + o0);
                float2 a1 = *(const float2*)(Cadd + o1);
                v0.x += a0.x * rc - a0.y * rs;
                v0.y += a0.x * rs + a0.y * rc;
                v1.x += a1.x * rc - a1.y * rs;
                v1.y += a1.x * rs + a1.y * rc;
                *(float2*)(D + o0) = v0;
                *(float2*)(D + o1) = v1;
            }
        }
    }
}

// ---------------------------------------------------------------------------
// Host orchestration
// ---------------------------------------------------------------------------
extern "C" void kernel_launch(void* const* d_in, const int* in_sizes, int n_in,
                              void* d_out, int out_size) {
    const float* x     = (const float*)d_in[0];
    const float* u1    = (const float*)d_in[1];
    const float* u2    = (const float*)d_in[2];
    const float* theta = (const float*)d_in[3];
    float* out = (float*)d_out;

    const int M = in_sizes[0] / DMODEL;   // 16384
    const int ew = (DM2 + 255) / 256;

    cudaFuncSetAttribute(hgemm_kernel, cudaFuncAttributeMaxDynamicSharedMemorySize,
                         SMEM_BYTES);

    float *pTa, *pTb, *pD0;
    __half *pT16a, *pT16b, *pFa, *pGa, *pFb, *pGb, *pBR, *pE2, *pDL, *pX;
    cudaGetSymbolAddress((void**)&pTa,   g_Ta);
    cudaGetSymbolAddress((void**)&pTb,   g_Tb);
    cudaGetSymbolAddress((void**)&pD0,   g_D0);
    cudaGetSymbolAddress((void**)&pT16a, g_T16a);
    cudaGetSymbolAddress((void**)&pT16b, g_T16b);
    cudaGetSymbolAddress((void**)&pFa,   g_Fa);
    cudaGetSymbolAddress((void**)&pGa,   g_Ga);
    cudaGetSymbolAddress((void**)&pFb,   g_Fb);
    cudaGetSymbolAddress((void**)&pGb,   g_Gb);
    cudaGetSymbolAddress((void**)&pBR,   g_BR);
    cudaGetSymbolAddress((void**)&pE2,   g_E2);
    cudaGetSymbolAddress((void**)&pDL,   g_DL);
    cudaGetSymbolAddress((void**)&pX,    g_X);

    // ---- skew for both layers (one launch) ----
    {
        dim3 grid(ew, 2);
        skew_batch_kernel<<<grid, 256>>>(u1, u2, pTa, pTb, pT16a, pT16b);
    }

    // ---- T2 GEMMs, both layers batched (z=2), MODE_CAYLEY ----
    {
        dim3 grid(DMODEL / BN, DMODEL / BM, 2);
        hgemm_kernel<<<grid, NTHREADS, SMEM_BYTES>>>(
            pT16a, pT16a, pTa, nullptr, pFa, pGa, MODE_CAYLEY,
            pT16b, pT16b, pTb, nullptr, pFb, pGb, MODE_CAYLEY,
            DMODEL, DMODEL, DMODEL, theta);
    }

    // ---- E GEMMs batched: z0 MODE_ROTR (D0, BR16), z1 MODE_H (E2_16) ----
    {
        dim3 grid(DMODEL / BN, DMODEL / BM, 2);
        hgemm_kernel<<<grid, NTHREADS, SMEM_BYTES>>>(
            pGa, pFa, nullptr, pD0, pBR, nullptr, MODE_ROTR,
            pGb, pFb, nullptr, nullptr, pE2, nullptr, MODE_H,
            DMODEL, DMODEL, DMODEL, theta);
    }

    // ---- Delta16 = fp16(D0 + BR @ E2) ----
    {
        dim3 grid(DMODEL / BN, DMODEL / BM, 1);
        hgemm_kernel<<<grid, NTHREADS, SMEM_BYTES>>>(
            pBR, pE2, pD0, nullptr, pDL, nullptr, MODE_H,
            nullptr, nullptr, nullptr, nullptr, nullptr, nullptr, 0,
            DMODEL, DMODEL, DMODEL, theta);
    }

    // ---- out = rot(x) + x @ Delta ----
    cvt_kernel<<<((M * DMODEL) / 4 + 255) / 256, 256>>>(x, pX, M * DMODEL);
    {
        dim3 grid(DMODEL / BN, M / BM, 1);
        hgemm_kernel<<<grid, NTHREADS, SMEM_BYTES>>>(
            pX, pDL, x, out, nullptr, nullptr, MODE_TOKEN,
            nullptr, nullptr, nullptr, nullptr, nullptr, nullptr, 0,
            M, DMODEL, DMODEL, theta);
    }
}

// round 16
// speedup vs baseline: 1.0843x; 1.0843x over previous
#include <cuda_runtime.h>
#include <cuda_fp16.h>
#include <math.h>

// Fixed problem dims: x[16384,2048], u[2048,2048]
#define DMODEL 2048
#define DM2 (DMODEL * DMODEL)
#define NTOK 16384

// ---- small-GEMM kernel geometry (R14: 64x128 CTA, 4 warps of 64x32, 4 CTA/SM)
#define SBM 64
#define SBN 128
#define BK 64
#define APAD 72    // 36 words % 32 == 4 -> conflict-free
#define BPAD 136   // 68 words % 32 == 4 -> conflict-free
#define SMEM_SMALL ((2 * SBM * APAD + 2 * BK * BPAD) * 2)    // 53248 -> 4 CTAs/SM

// ---- token-GEMM kernel geometry (square warps: 128x128 CTA, 4 warps of 64x64)
#define TBM 128
#define TBN 128
#define SMEM_TOK ((2 * TBM * APAD + 2 * BK * BPAD) * 2)      // 71680 -> 3 CTAs/SM

// Epilogue modes (small kernel)
#define MODE_CAYLEY 1
#define MODE_ROTR   2
#define MODE_H      3

// ---------------------------------------------------------------------------
// Scratch
// ---------------------------------------------------------------------------
__device__ float g_Ta[DM2], g_Tb[DM2];
__device__ float g_D0[DM2];
__device__ __half g_T16a[DM2], g_T16b[DM2];
__device__ __half g_Fa[DM2], g_Ga[DM2];
__device__ __half g_Fb[DM2], g_Gb[DM2];
__device__ __half g_BR[DM2];
__device__ __half g_E2[DM2];
__device__ __half g_DL[DM2];
__device__ __half g_X[NTOK * DMODEL];

// ---------------------------------------------------------------------------
// Elementwise kernels
// ---------------------------------------------------------------------------
__global__ void skew_batch_kernel(const float* __restrict__ W0, const float* __restrict__ W1,
                                  float* __restrict__ T0, float* __restrict__ T1,
                                  __half* __restrict__ H0, __half* __restrict__ H1) {
    int idx = blockIdx.x * blockDim.x + threadIdx.x;
    if (idx >= DM2) return;
    const float* W = blockIdx.y ? W1 : W0;
    float* T = blockIdx.y ? T1 : T0;
    __half* H = blockIdx.y ? H1 : H0;
    int i = idx / DMODEL;
    int j = idx % DMODEL;
    float v = 0.5f * (W[j * DMODEL + i] - W[idx]);
    T[idx] = v;
    H[idx] = __float2half_rn(v);
}

__global__ void cvt_kernel(const float* __restrict__ X, __half* __restrict__ H, int n) {
    int i = (blockIdx.x * blockDim.x + threadIdx.x) * 4;
    if (i >= n) return;
    float4 v = *(const float4*)(X + i);
    __half2* Hp = (__half2*)(H + i);
    Hp[0] = __floats2half2_rn(v.x, v.y);
    Hp[1] = __floats2half2_rn(v.z, v.w);
}

// ---------------------------------------------------------------------------
// Shared PTX macros
// ---------------------------------------------------------------------------
#define CPASYNC16(saddr, gptr) \
    asm volatile("cp.async.cg.shared.global [%0], [%1], 16;\n" :: "r"(saddr), "l"(gptr))
#define CP_COMMIT() asm volatile("cp.async.commit_group;\n" ::)
#define CP_WAIT(n)  asm volatile("cp.async.wait_group %0;\n" :: "n"(n))
#define LDSM4(r, addr) \
    asm volatile("ldmatrix.sync.aligned.m8n8.x4.shared.b16 {%0,%1,%2,%3}, [%4];\n" \
                 : "=r"((r)[0]), "=r"((r)[1]), "=r"((r)[2]), "=r"((r)[3]) : "r"(addr))
#define LDSM4T(r, addr) \
    asm volatile("ldmatrix.sync.aligned.m8n8.x4.trans.shared.b16 {%0,%1,%2,%3}, [%4];\n" \
                 : "=r"((r)[0]), "=r"((r)[1]), "=r"((r)[2]), "=r"((r)[3]) : "r"(addr))
#define MMA_F16(c, a, b) \
    asm volatile("mma.sync.aligned.m16n8k16.row.col.f32.f16.f16.f32 " \
                 "{%0,%1,%2,%3},{%4,%5,%6,%7},{%8,%9},{%0,%1,%2,%3};\n" \
                 : "+f"((c)[0]), "+f"((c)[1]), "+f"((c)[2]), "+f"((c)[3]) \
                 : "r"((a)[0]), "r"((a)[1]), "r"((a)[2]), "r"((a)[3]), \
                   "r"((b)[0]), "r"((b)[1]))

// ===========================================================================
// SMALL kernel: 64x128 CTA, 128 thr / 4 warps (64x32 tiles), 4 CTAs/SM.
// ===========================================================================
__device__ __forceinline__ int saoff(int s) { return s * (SBM * APAD); }
__device__ __forceinline__ int sboff(int s) { return 2 * SBM * APAD + s * (BK * BPAD); }

__global__ __launch_bounds__(128, 4)
void hgemm_small(const __half* __restrict__ A0, const __half* __restrict__ B0,
                 const float* __restrict__ C0, float* __restrict__ D0_,
                 __half* __restrict__ H10, __half* __restrict__ H20, int mode0,
                 const __half* __restrict__ A1, const __half* __restrict__ B1,
                 const float* __restrict__ C1, float* __restrict__ D1_,
                 __half* __restrict__ H11, __half* __restrict__ H21, int mode1,
                 int M, int N, int K, const float* __restrict__ theta) {
    extern __shared__ __half sm[];
    const unsigned smbase = (unsigned)__cvta_generic_to_shared(sm);

    const int z = blockIdx.z;
    const __half* A = z ? A1 : A0;
    const __half* B = z ? B1 : B0;
    const float* Cadd = z ? C1 : C0;
    float* D = z ? D1_ : D0_;
    __half* H1 = z ? H11 : H10;
    __half* H2 = z ? H21 : H20;
    const int mode = z ? mode1 : mode0;

    const int tid = threadIdx.x;
    const int lane = tid & 31;
    const int wn = tid >> 5;          // 0..3: 32-col slab
    const int bm = blockIdx.y * SBM;
    const int bn = blockIdx.x * SBN;

    float c[4][4][4];
#pragma unroll
    for (int i = 0; i < 4; i++)
#pragma unroll
        for (int j = 0; j < 4; j++)
#pragma unroll
            for (int q = 0; q < 4; q++) c[i][j][q] = 0.0f;

    const int NIT = K / BK;

    auto load_stage = [&](int s, int k0) {
#pragma unroll
        for (int i = 0; i < 4; i++) {            // A: 64 x 64 = 512 chunks
            int v = tid + (i << 7);
            int ar = v >> 3, ac = (v & 7) * 8;
            const __half* ga = A + (size_t)(bm + ar) * K + k0 + ac;
            CPASYNC16(smbase + (unsigned)(saoff(s) + ar * APAD + ac) * 2, ga);
        }
#pragma unroll
        for (int i = 0; i < 8; i++) {            // B: 64 x 128 = 1024 chunks
            int v = tid + (i << 7);
            int br = v >> 4, bc = (v & 15) * 8;
            const __half* gb = B + (size_t)(k0 + br) * N + bn + bc;
            CPASYNC16(smbase + (unsigned)(sboff(s) + br * BPAD + bc) * 2, gb);
        }
        CP_COMMIT();
    };

    auto compute_stage = [&](int s) {
#pragma unroll
        for (int ks = 0; ks < 4; ks++) {
            unsigned ar[4][4];
#pragma unroll
            for (int i = 0; i < 4; i++) {
                int row = i * 16 + (lane & 15);
                int col = ((lane >> 4) << 3) + ks * 16;
                LDSM4(ar[i], smbase + (unsigned)(saoff(s) + row * APAD + col) * 2);
            }
            unsigned br[4][2];
#pragma unroll
            for (int t = 0; t < 2; t++) {
                int row = ks * 16 + (lane & 15);
                int col = wn * 32 + t * 16 + ((lane >> 4) << 3);
                unsigned r[4];
                LDSM4T(r, smbase + (unsigned)(sboff(s) + row * BPAD + col) * 2);
                br[t * 2][0] = r[0]; br[t * 2][1] = r[1];
                br[t * 2 + 1][0] = r[2]; br[t * 2 + 1][1] = r[3];
            }
#pragma unroll
            for (int i = 0; i < 4; i++)
#pragma unroll
                for (int j = 0; j < 4; j++)
                    MMA_F16(c[i][j], ar[i], br[j]);
        }
    };

    load_stage(0, 0);
    for (int it = 0; it < NIT; ++it) {
        CP_WAIT(0);
        __syncthreads();
        if (it + 1 < NIT) load_stage((it + 1) & 1, (it + 1) * BK);
        compute_stage(it & 1);
    }

    float rc = 1.0f, rs = 0.0f;
    if (mode == MODE_ROTR) {
        float th = *theta;
        rc = cosf(th);
        rs = sinf(th);
    }
    const int gr = lane >> 2;
    const int gc = lane & 3;

#pragma unroll
    for (int i = 0; i < 4; i++) {
#pragma unroll
        for (int j = 0; j < 4; j++) {
            int row0 = bm + i * 16 + gr;
            int row1 = row0 + 8;
            int col = bn + wn * 32 + j * 8 + gc * 2;
            size_t o0 = (size_t)row0 * N + col;
            size_t o1 = (size_t)row1 * N + col;
            float2 v0 = make_float2(c[i][j][0], c[i][j][1]);
            float2 v1 = make_float2(c[i][j][2], c[i][j][3]);

            if (mode == MODE_CAYLEY) {
                float2 t0 = *(const float2*)(Cadd + o0);
                float2 t1 = *(const float2*)(Cadd + o1);
                float f0x = v0.x + (row0 == col ? 1.0f : 0.0f);
                float f0y = v0.y + (row0 == col + 1 ? 1.0f : 0.0f);
                float f1x = v1.x + (row1 == col ? 1.0f : 0.0f);
                float f1y = v1.y + (row1 == col + 1 ? 1.0f : 0.0f);
                *(__half2*)(H1 + o0) = __floats2half2_rn(f0x, f0y);
                *(__half2*)(H1 + o1) = __floats2half2_rn(f1x, f1y);
                *(__half2*)(H2 + o0) = __floats2half2_rn(2.0f * (t0.x + v0.x),
                                                         2.0f * (t0.y + v0.y));
                *(__half2*)(H2 + o1) = __floats2half2_rn(2.0f * (t1.x + v1.x),
                                                         2.0f * (t1.y + v1.y));
            } else if (mode == MODE_ROTR) {
                float2 r0 = make_float2(v0.x * rc - v0.y * rs, v0.x * rs + v0.y * rc);
                float2 r1 = make_float2(v1.x * rc - v1.y * rs, v1.x * rs + v1.y * rc);
                *(float2*)(D + o0) = r0;
                *(float2*)(D + o1) = r1;
                float a0x = (row0 == col ? rc : (row0 == col + 1 ? -rs : 0.0f));
                float a0y = (row0 == col ? rs : (row0 == col + 1 ?  rc : 0.0f));
                float a1x = (row1 == col ? rc : (row1 == col + 1 ? -rs : 0.0f));
                float a1y = (row1 == col ? rs : (row1 == col + 1 ?  rc : 0.0f));
                *(__half2*)(H1 + o0) = __floats2half2_rn(r0.x + a0x, r0.y + a0y);
                *(__half2*)(H1 + o1) = __floats2half2_rn(r1.x + a1x, r1.y + a1y);
            } else {  // MODE_H
                if (Cadd) {
                    float2 a0 = *(const float2*)(Cadd + o0);
                    float2 a1 = *(const float2*)(Cadd + o1);
                    v0.x += a0.x; v0.y += a0.y;
                    v1.x += a1.x; v1.y += a1.y;
                }
                *(__half2*)(H1 + o0) = __floats2half2_rn(v0.x, v0.y);
                *(__half2*)(H1 + o1) = __floats2half2_rn(v1.x, v1.y);
            }
        }
    }
}

// ===========================================================================
// TOKEN kernel: 128x128 CTA, 128 thr / 4 warps (64x64 tiles -> min smem/MAC),
// 3 CTAs/SM. out = acc + rot(Cadd). fp32 out.
// ===========================================================================
__device__ __forceinline__ int taoff(int s) { return s * (TBM * APAD); }
__device__ __forceinline__ int tboff(int s) { return 2 * TBM * APAD + s * (BK * BPAD); }

__global__ __launch_bounds__(128, 3)
void hgemm_token(const __half* __restrict__ A, const __half* __restrict__ B,
                 const float* __restrict__ Cadd, float* __restrict__ D,
                 int M, int N, int K, const float* __restrict__ theta) {
    extern __shared__ __half sm[];
    const unsigned smbase = (unsigned)__cvta_generic_to_shared(sm);

    const int tid = threadIdx.x;
    const int lane = tid & 31;
    const int warp = tid >> 5;       // 0..3
    const int wm = warp >> 1;        // 0..1 (64-row slab)
    const int wn = warp & 1;         // 0..1 (64-col slab)
    const int bm = blockIdx.y * TBM;
    const int bn = blockIdx.x * TBN;

    float c[4][8][4];
#pragma unroll
    for (int i = 0; i < 4; i++)
#pragma unroll
        for (int j = 0; j < 8; j++)
#pragma unroll
            for (int q = 0; q < 4; q++) c[i][j][q] = 0.0f;

    const int NIT = K / BK;

    auto load_stage = [&](int s, int k0) {
#pragma unroll
        for (int i = 0; i < 8; i++) {            // A: 128 x 64 = 1024 chunks
            int v = tid + (i << 7);
            int ar = v >> 3, ac = (v & 7) * 8;
            const __half* ga = A + (size_t)(bm + ar) * K + k0 + ac;
            CPASYNC16(smbase + (unsigned)(taoff(s) + ar * APAD + ac) * 2, ga);
        }
#pragma unroll
        for (int i = 0; i < 8; i++) {            // B: 64 x 128 = 1024 chunks
            int v = tid + (i << 7);
            int br = v >> 4, bc = (v & 15) * 8;
            const __half* gb = B + (size_t)(k0 + br) * N + bn + bc;
            CPASYNC16(smbase + (unsigned)(tboff(s) + br * BPAD + bc) * 2, gb);
        }
        CP_COMMIT();
    };

    auto compute_stage = [&](int s) {
#pragma unroll
        for (int ks = 0; ks < 4; ks++) {
            unsigned ar[4][4];
#pragma unroll
            for (int i = 0; i < 4; i++) {
                int row = wm * 64 + i * 16 + (lane & 15);
                int col = ((lane >> 4) << 3) + ks * 16;
                LDSM4(ar[i], smbase + (unsigned)(taoff(s) + row * APAD + col) * 2);
            }
#pragma unroll
            for (int th = 0; th < 2; th++) {
                unsigned br[4][2];
#pragma unroll
                for (int t = 0; t < 2; t++) {
                    int row = ks * 16 + (lane & 15);
                    int col = wn * 64 + th * 32 + t * 16 + ((lane >> 4) << 3);
                    unsigned r[4];
                    LDSM4T(r, smbase + (unsigned)(tboff(s) + row * BPAD + col) * 2);
                    br[t * 2][0] = r[0]; br[t * 2][1] = r[1];
                    br[t * 2 + 1][0] = r[2]; br[t * 2 + 1][1] = r[3];
                }
#pragma unroll
                for (int i = 0; i < 4; i++)
#pragma unroll
                    for (int j = 0; j < 4; j++)
                        MMA_F16(c[i][th * 4 + j], ar[i], br[j]);
            }
        }
    };

    load_stage(0, 0);
    for (int it = 0; it < NIT; ++it) {
        CP_WAIT(0);
        __syncthreads();
        if (it + 1 < NIT) load_stage((it + 1) & 1, (it + 1) * BK);
        compute_stage(it & 1);
    }

    float th_ = *theta;
    float rc = cosf(th_), rs = sinf(th_);
    const int gr = lane >> 2;
    const int gc = lane & 3;

#pragma unroll
    for (int i = 0; i < 4; i++) {
#pragma unroll
        for (int j = 0; j < 8; j++) {
            int row0 = bm + wm * 64 + i * 16 + gr;
            int row1 = row0 + 8;
            int col = bn + wn * 64 + j * 8 + gc * 2;
            size_t o0 = (size_t)row0 * N + col;
            size_t o1 = (size_t)row1 * N + col;
            float2 v0 = make_float2(c[i][j][0], c[i][j][1]);
            float2 v1 = make_float2(c[i][j][2], c[i][j][3]);
            float2 a0 = *(const float2*)(Cadd + o0);
            float2 a1 = *(const float2*)(Cadd + o1);
            v0.x += a0.x * rc - a0.y * rs;
            v0.y += a0.x * rs + a0.y * rc;
            v1.x += a1.x * rc - a1.y * rs;
            v1.y += a1.x * rs + a1.y * rc;
            *(float2*)(D + o0) = v0;
            *(float2*)(D + o1) = v1;
        }
    }
}

// ---------------------------------------------------------------------------
// Host orchestration
// ---------------------------------------------------------------------------
extern "C" void kernel_launch(void* const* d_in, const int* in_sizes, int n_in,
                              void* d_out, int out_size) {
    const float* x     = (const float*)d_in[0];
    const float* u1    = (const float*)d_in[1];
    const float* u2    = (const float*)d_in[2];
    const float* theta = (const float*)d_in[3];
    float* out = (float*)d_out;

    const int M = in_sizes[0] / DMODEL;   // 16384
    const int ew = (DM2 + 255) / 256;

    cudaFuncSetAttribute(hgemm_small, cudaFuncAttributeMaxDynamicSharedMemorySize,
                         SMEM_SMALL);
    cudaFuncSetAttribute(hgemm_token, cudaFuncAttributeMaxDynamicSharedMemorySize,
                         SMEM_TOK);

    float *pTa, *pTb, *pD0;
    __half *pT16a, *pT16b, *pFa, *pGa, *pFb, *pGb, *pBR, *pE2, *pDL, *pX;
    cudaGetSymbolAddress((void**)&pTa,   g_Ta);
    cudaGetSymbolAddress((void**)&pTb,   g_Tb);
    cudaGetSymbolAddress((void**)&pD0,   g_D0);
    cudaGetSymbolAddress((void**)&pT16a, g_T16a);
    cudaGetSymbolAddress((void**)&pT16b, g_T16b);
    cudaGetSymbolAddress((void**)&pFa,   g_Fa);
    cudaGetSymbolAddress((void**)&pGa,   g_Ga);
    cudaGetSymbolAddress((void**)&pFb,   g_Fb);
    cudaGetSymbolAddress((void**)&pGb,   g_Gb);
    cudaGetSymbolAddress((void**)&pBR,   g_BR);
    cudaGetSymbolAddress((void**)&pE2,   g_E2);
    cudaGetSymbolAddress((void**)&pDL,   g_DL);
    cudaGetSymbolAddress((void**)&pX,    g_X);

    // ---- skew for both layers ----
    {
        dim3 grid(ew, 2);
        skew_batch_kernel<<<grid, 256>>>(u1, u2, pTa, pTb, pT16a, pT16b);
    }

    // ---- T2 GEMMs (z=2), MODE_CAYLEY ----
    {
        dim3 grid(DMODEL / SBN, DMODEL / SBM, 2);
        hgemm_small<<<grid, 128, SMEM_SMALL>>>(
            pT16a, pT16a, pTa, nullptr, pFa, pGa, MODE_CAYLEY,
            pT16b, pT16b, pTb, nullptr, pFb, pGb, MODE_CAYLEY,
            DMODEL, DMODEL, DMODEL, theta);
    }

    // ---- E GEMMs (z=2): z0 MODE_ROTR, z1 MODE_H ----
    {
        dim3 grid(DMODEL / SBN, DMODEL / SBM, 2);
        hgemm_small<<<grid, 128, SMEM_SMALL>>>(
            pGa, pFa, nullptr, pD0, pBR, nullptr, MODE_ROTR,
            pGb, pFb, nullptr, nullptr, pE2, nullptr, MODE_H,
            DMODEL, DMODEL, DMODEL, theta);
    }

    // ---- Delta16 = fp16(D0 + BR @ E2) ----
    {
        dim3 grid(DMODEL / SBN, DMODEL / SBM, 1);
        hgemm_small<<<grid, 128, SMEM_SMALL>>>(
            pBR, pE2, pD0, nullptr, pDL, nullptr, MODE_H,
            nullptr, nullptr, nullptr, nullptr, nullptr, nullptr, 0,
            DMODEL, DMODEL, DMODEL, theta);
    }

    // ---- out = rot(x) + x @ Delta  (square-warp token kernel) ----
    cvt_kernel<<<((M * DMODEL) / 4 + 255) / 256, 256>>>(x, pX, M * DMODEL);
    {
        dim3 grid(DMODEL / TBN, M / TBM, 1);
        hgemm_token<<<grid, 128, SMEM_TOK>>>(
            pX, pDL, x, out, M, DMODEL, DMODEL, theta);
    }
}